// round 17
// baseline (speedup 1.0000x reference)
#include <cuda_runtime.h>
#include <math.h>
#include <stdint.h>

#define BHn   96
#define Nn    1024
#define Cc    64
#define RCc   32
#define RNn   128
#define NM1   1023
#define ROWS_TOT (BHn*NM1)   /* 98208 */
#define KTOP  16
#define BUDGET 256

typedef unsigned long long u64;
typedef unsigned u32;

// ---------------- scratch ----------------
__device__ __align__(16) float g_qp[BHn*Nn*RCc];
__device__ __align__(16) float g_kp[BHn*Nn*RCc];
__device__ __align__(16) float g_kp2p[8*BHn*RCc*RNn];
__device__ __align__(16) float g_kp2[BHn*RCc*RNn];
__device__ __align__(16) float g_basis[RNn*Nn];

// packed f32x2 helpers (bit-identical to scalar fma per component)
__device__ __forceinline__ void fma2(u64 &d, u64 a, u64 b) {
    asm("fma.rn.f32x2 %0, %1, %2, %0;" : "+l"(d) : "l"(a), "l"(b));
}
__device__ __forceinline__ u64 pk2(float x, float y) {
    u64 r; asm("mov.b64 %0, {%1, %2};" : "=l"(r) : "f"(x), "f"(y)); return r;
}
__device__ __forceinline__ void upk2(u64 v, float &x, float &y) {
    asm("mov.b64 {%0, %1}, %2;" : "=f"(x), "=f"(y) : "l"(v));
}

// ---------------- exact warp k-th largest over NV positive floats/lane ----------------
// Binary bit-descent with float-pipe counting; candidates <=32 finished by a
// 32-lane bitonic sort (exact rank with multiplicity). Returns kth-largest bits.
template<int NV>
__device__ __forceinline__ u32 warp_kth_float(const float* v, int k, u32* sb, int lane) {
    const unsigned FULL = 0xffffffffu;
    float mx = v[0], mn = v[0];
    #pragma unroll
    for (int i = 1; i < NV; i++) { mx = fmaxf(mx, v[i]); mn = fminf(mn, v[i]); }
    #pragma unroll
    for (int off = 16; off; off >>= 1) {
        mx = fmaxf(mx, __shfl_xor_sync(FULL, mx, off));
        mn = fminf(mn, __shfl_xor_sync(FULL, mn, off));
    }
    u32 Mb = __float_as_uint(mx), mb = __float_as_uint(mn);
    if (Mb == mb) return Mb;
    int hb = 31 - __clz(Mb ^ mb);          // <= 30 for positive floats
    u32 thr = Mb & ~((2u << hb) - 1u);     // common prefix, low bits zero
    float C_lo = (float)(NV*32);
    float C_up = 0.0f;
    const float kf = (float)k;
    int b = hb;
    #pragma unroll 1
    for (; b >= 0; b--) {
        float tf = __uint_as_float(thr | (1u << b));
        float c0 = 0.f, c1 = 0.f, c2 = 0.f, c3 = 0.f;
        #pragma unroll
        for (int i = 0; i < NV/4; i++) {
            if (v[4*i+0] >= tf) c0 += 1.0f;
            if (v[4*i+1] >= tf) c1 += 1.0f;
            if (v[4*i+2] >= tf) c2 += 1.0f;
            if (v[4*i+3] >= tf) c3 += 1.0f;
        }
        float cf = (c0 + c1) + (c2 + c3);
        #pragma unroll
        for (int off = 16; off; off >>= 1) cf += __shfl_xor_sync(FULL, cf, off);
        if (cf >= kf) { thr |= (1u << b); C_lo = cf; }
        else           C_up = cf;
        if (C_lo - C_up <= 32.0f) { b--; break; }
    }
    if (b >= 0) {
        int kk = k - (int)C_up;            // rank within window (1..32)
        u32 cmp = thr >> (b+1);
        unsigned ltm = (1u << lane) - 1u;
        int base = 0;
        #pragma unroll
        for (int i = 0; i < NV; i++) {
            u32 u = __float_as_uint(v[i]);
            bool f = (u >> (b+1)) == cmp;
            unsigned bal = __ballot_sync(FULL, f);
            if (f) sb[base + __popc(bal & ltm)] = u;
            base += __popc(bal);
        }
        __syncwarp();
        float cand = (lane < base) ? __uint_as_float(sb[lane]) : 0.0f;
        // 32-lane bitonic sort, descending (positive floats: float order == bit order)
        #pragma unroll
        for (int kq = 2; kq <= 32; kq <<= 1) {
            #pragma unroll
            for (int j = kq >> 1; j > 0; j >>= 1) {
                float other = __shfl_xor_sync(FULL, cand, j);
                bool smaller = ((lane & j) == 0);
                bool dir = ((lane & kq) == 0);
                cand = (dir == smaller) ? fmaxf(cand, other) : fminf(cand, other);
            }
        }
        thr = __shfl_sync(FULL, __float_as_uint(cand), kk - 1);
        __syncwarp();
    }
    return thr;
}

// ---------------- fused prep: basis threshold + q projection + k projection ----------------
__global__ __launch_bounds__(256) void k_prep(const float* __restrict__ q,
                                              const float* __restrict__ kin,
                                              const float* __restrict__ wq,
                                              const float* __restrict__ bq,
                                              const float* __restrict__ wk,
                                              const float* __restrict__ bk,
                                              const float* __restrict__ pb) {
    int bid = blockIdx.x;
    if (bid < 512) {
        int i = bid*256 + threadIdx.x;
        if (i < RNn*Nn) {
            int j = i >> 7, c = i & 127;
            float v = fabsf(pb[i]);
            g_basis[(size_t)c*Nn + j] = (v > 0.02f) ? v : 0.0f;
        }
        return;
    }
    const float* x;
    const float* w;
    const float* b;
    float* out;
    int pbid;
    if (bid < 1280) { x = q;   w = wq; b = bq; out = g_qp; pbid = bid - 512; }
    else            { x = kin; w = wk; b = bk; out = g_kp; pbid = bid - 1280; }

    int warp = threadIdx.x >> 5, lane = threadIdx.x & 31;
    int row0 = (pbid*8 + warp)*16;
    float wr[64];
    #pragma unroll
    for (int c4 = 0; c4 < 16; c4++) {
        float4 t = *(const float4*)(w + lane*64 + c4*4);
        wr[c4*4+0]=t.x; wr[c4*4+1]=t.y; wr[c4*4+2]=t.z; wr[c4*4+3]=t.w;
    }
    float bias = b[lane];
    for (int r = 0; r < 16; r++) {
        int row = row0 + r;
        float qlo = x[(size_t)row*64 + lane];
        float qhi = x[(size_t)row*64 + 32 + lane];
        float acc = 0.0f;
        #pragma unroll
        for (int c = 0; c < 32; c++) acc = fmaf(__shfl_sync(0xffffffffu, qlo, c), wr[c],    acc);
        #pragma unroll
        for (int c = 0; c < 32; c++) acc = fmaf(__shfl_sync(0xffffffffu, qhi, c), wr[32+c], acc);
        out[(size_t)row*32 + lane] = acc + bias;
    }
}

// ---------------- kp2 partial ----------------
__global__ __launch_bounds__(256) void k_kp2_part(const float* __restrict__ proj_n) {
    __shared__ float kp_s[128*32];
    __shared__ float pj_s[128*64];
    int bh = blockIdx.x, ch = blockIdx.y, half = blockIdx.z;
    int n0 = ch*128, rnb = half*64, tid = threadIdx.x;
    const float4* src = (const float4*)(g_kp + ((size_t)bh*Nn + n0)*32);
    for (int i = tid; i < 1024; i += 256) ((float4*)kp_s)[i] = src[i];
    for (int i = tid; i < 2048; i += 256) {
        int r = i >> 4, c4 = i & 15;
        ((float4*)pj_s)[i] = *((const float4*)(proj_n + (size_t)(n0+r)*128 + rnb) + c4);
    }
    __syncthreads();
    int rc0 = (tid & 7)*4;
    int rn0 = (tid >> 3)*2;
    float a00=0,a01=0,a10=0,a11=0,a20=0,a21=0,a30=0,a31=0;
    #pragma unroll 4
    for (int n = 0; n < 128; n++) {
        float4 a = *(const float4*)(kp_s + n*32 + rc0);
        float2 p = *(const float2*)(pj_s + n*64 + rn0);
        a00 = fmaf(a.x, p.x, a00); a01 = fmaf(a.x, p.y, a01);
        a10 = fmaf(a.y, p.x, a10); a11 = fmaf(a.y, p.y, a11);
        a20 = fmaf(a.z, p.x, a20); a21 = fmaf(a.z, p.y, a21);
        a30 = fmaf(a.w, p.x, a30); a31 = fmaf(a.w, p.y, a31);
    }
    float* outp = g_kp2p + ((size_t)ch*BHn + bh)*4096 + rnb + rn0;
    *(float2*)(outp + (rc0+0)*128) = make_float2(a00, a01);
    *(float2*)(outp + (rc0+1)*128) = make_float2(a10, a11);
    *(float2*)(outp + (rc0+2)*128) = make_float2(a20, a21);
    *(float2*)(outp + (rc0+3)*128) = make_float2(a30, a31);
}

__global__ void k_kp2_red() {
    int i = blockIdx.x*256 + threadIdx.x;
    if (i < BHn*RCc*RNn) {
        float s = 0.0f;
        #pragma unroll
        for (int ch = 0; ch < 8; ch++) s += g_kp2p[(size_t)ch*BHn*4096 + i];
        g_kp2[i] = s;
    }
}

// ---------------- fused main: 2 rows per warp (shared kp2 loads) ----------------
__global__ __launch_bounds__(128) void k_main(float* __restrict__ out_coef,
                                              float* __restrict__ out_approx,
                                              float* __restrict__ out_mask) {
    __shared__ u64 sm_pair[4][2][16];
    __shared__ u32 sm_cand[4][32];
    int warp = threadIdx.x >> 5, lane = threadIdx.x & 31;
    const unsigned FULL = 0xffffffffu;
    int rr0 = blockIdx.x*8 + warp*2;
    int bhA = rr0 / NM1,       nA = rr0 - bhA*NM1 + 1;
    int rr1 = rr0 + 1;
    int bhB = rr1 / NM1,       nB = rr1 - bhB*NM1 + 1;

    // ---- cheap attn for both rows, sharing kv loads when same bh ----
    float qvA = g_qp[((size_t)bhA*Nn + nA)*32 + lane];
    float qvB = g_qp[((size_t)bhB*Nn + nB)*32 + lane];
    u64 a01[2] = {0ULL, 0ULL}, a23[2] = {0ULL, 0ULL};
    const ulonglong2* kbA = (const ulonglong2*)(g_kp2 + (size_t)bhA*4096);
    if (bhA == bhB) {
        #pragma unroll
        for (int rc = 0; rc < 32; rc++) {
            ulonglong2 kv = __ldg(kbA + rc*32 + lane);
            float aA = __shfl_sync(FULL, qvA, rc);
            float aB = __shfl_sync(FULL, qvB, rc);
            u64 aaA = pk2(aA, aA), aaB = pk2(aB, aB);
            fma2(a01[0], kv.x, aaA);
            fma2(a23[0], kv.y, aaA);
            fma2(a01[1], kv.x, aaB);
            fma2(a23[1], kv.y, aaB);
        }
    } else {
        const ulonglong2* kbB = (const ulonglong2*)(g_kp2 + (size_t)bhB*4096);
        #pragma unroll
        for (int rc = 0; rc < 32; rc++) {
            ulonglong2 kvA = __ldg(kbA + rc*32 + lane);
            ulonglong2 kvB = __ldg(kbB + rc*32 + lane);
            float aA = __shfl_sync(FULL, qvA, rc);
            float aB = __shfl_sync(FULL, qvB, rc);
            u64 aaA = pk2(aA, aA), aaB = pk2(aB, aB);
            fma2(a01[0], kvA.x, aaA);
            fma2(a23[0], kvA.y, aaA);
            fma2(a01[1], kvB.x, aaB);
            fma2(a23[1], kvB.y, aaB);
        }
    }

    const float scale = 0.28867513459481287f;
    unsigned ltm = (1u << lane) - 1u;

    // ---- per-row back half ----
    #pragma unroll 1
    for (int s = 0; s < 2; s++) {
        int rr = rr0 + s;
        int bh = s ? bhB : bhA;
        int n  = s ? nB  : nA;

        float ax, ay, az, aw;
        upk2(a01[s], ax, ay);
        upk2(a23[s], az, aw);
        float l[4] = {ax*scale, ay*scale, az*scale, aw*scale};
        float m = fmaxf(fmaxf(l[0], l[1]), fmaxf(l[2], l[3]));
        #pragma unroll
        for (int off = 16; off; off >>= 1) m = fmaxf(m, __shfl_xor_sync(FULL, m, off));
        float e[4], ssum = 0.0f;
        #pragma unroll
        for (int j = 0; j < 4; j++) { e[j] = expf(l[j] - m); ssum += e[j]; }
        #pragma unroll
        for (int off = 16; off; off >>= 1) ssum += __shfl_xor_sync(FULL, ssum, off);
        float c[4];
        #pragma unroll
        for (int j = 0; j < 4; j++) c[j] = e[j] / ssum;

        // topk16 via exact float bit-descent
        u32 T = warp_kth_float<4>(c, KTOP, sm_cand[warp], lane);
        float Tf = __uint_as_float(T);

        bool gt[4], eq[4];
        #pragma unroll
        for (int j = 0; j < 4; j++) { gt[j] = c[j] > Tf; eq[j] = c[j] == Tf; }
        unsigned balg0 = __ballot_sync(FULL, gt[0]), balg1 = __ballot_sync(FULL, gt[1]);
        unsigned balg2 = __ballot_sync(FULL, gt[2]), balg3 = __ballot_sync(FULL, gt[3]);
        unsigned bale0 = __ballot_sync(FULL, eq[0]), bale1 = __ballot_sync(FULL, eq[1]);
        unsigned bale2 = __ballot_sync(FULL, eq[2]), bale3 = __ballot_sync(FULL, eq[3]);
        int mgt = __popc(balg0) + __popc(balg1) + __popc(balg2) + __popc(balg3);
        int need = KTOP - mgt;
        int eq_before = __popc(bale0 & ltm) + __popc(bale1 & ltm) + __popc(bale2 & ltm) + __popc(bale3 & ltm);
        bool sel[4];
        int eqrun = eq_before;
        #pragma unroll
        for (int j = 0; j < 4; j++) {
            sel[j] = gt[j] || (eq[j] && (eqrun < need));
            if (eq[j]) eqrun++;
        }

        // coef row
        {
            float4 o;
            o.x = sel[0] ? c[0] : 0.0f;
            o.y = sel[1] ? c[1] : 0.0f;
            o.z = sel[2] ? c[2] : 0.0f;
            o.w = sel[3] ? c[3] : 0.0f;
            *(float4*)(out_coef + (size_t)rr*128 + lane*4) = o;
        }

        // pack 16 selected (idx,val) pairs, ascending idx
        unsigned bs0 = __ballot_sync(FULL, sel[0]), bs1 = __ballot_sync(FULL, sel[1]);
        unsigned bs2 = __ballot_sync(FULL, sel[2]), bs3 = __ballot_sync(FULL, sel[3]);
        int run = __popc(bs0 & ltm) + __popc(bs1 & ltm) + __popc(bs2 & ltm) + __popc(bs3 & ltm);
        #pragma unroll
        for (int j = 0; j < 4; j++) {
            if (sel[j]) { sm_pair[warp][s][run] = ((u64)(unsigned)(lane*4 + j) << 32) | (u64)__float_as_uint(c[j]); run++; }
        }
        __syncwarp();

        // sparse SpMM: ascending idx, packed f32x2 (order identical to reference)
        u64 acc[16];
        #pragma unroll
        for (int j = 0; j < 16; j++) acc[j] = 0ULL;
        #pragma unroll 4
        for (int t = 0; t < 16; t++) {
            u64 pr = sm_pair[warp][s][t];
            int   ci = (int)(pr >> 32);
            float v  = __uint_as_float((u32)pr);
            u64 vv = pk2(v, v);
            const ulonglong2* bp = (const ulonglong2*)(g_basis + (size_t)ci*Nn);
            #pragma unroll
            for (int j = 0; j < 8; j++) {
                ulonglong2 x = __ldg(bp + j*32 + lane);
                fma2(acc[2*j],   x.x, vv);
                fma2(acc[2*j+1], x.y, vv);
            }
        }

        // approx_attn (streaming)
        float* outp = out_approx + (size_t)rr*1024;
        #pragma unroll
        for (int j = 0; j < 8; j++) {
            float4 o;
            upk2(acc[2*j],   o.x, o.y);
            upk2(acc[2*j+1], o.z, o.w);
            __stcs((float4*)outp + j*32 + lane, o);
        }

        // exact top-256 threshold via float bit-descent
        float v32[32];
        #pragma unroll
        for (int j = 0; j < 8; j++) {
            upk2(acc[2*j],   v32[4*j+0], v32[4*j+1]);
            upk2(acc[2*j+1], v32[4*j+2], v32[4*j+3]);
        }
        u32 prefix = warp_kth_float<32>(v32, BUDGET, sm_cand[warp], lane);
        float pf = __uint_as_float(prefix);

        // mask row
        float* mout = out_mask + ((size_t)bh*Nn + n)*Nn;
        #pragma unroll
        for (int j = 0; j < 8; j++) {
            float4 mo;
            mo.x = (v32[4*j+0] >= pf) ? 1.0f : 0.0f;
            mo.y = (v32[4*j+1] >= pf) ? 1.0f : 0.0f;
            mo.z = (v32[4*j+2] >= pf) ? 1.0f : 0.0f;
            mo.w = (v32[4*j+3] >= pf) ? 1.0f : 0.0f;
            __stcs((float4*)mout + j*32 + lane, mo);
        }

        // cls row of this bh (exactly one warp-row per bh has n==1)
        if (n == 1) {
            float* cout = out_mask + (size_t)bh*Nn*Nn;
            float4 one4 = {1.0f, 1.0f, 1.0f, 1.0f};
            #pragma unroll
            for (int j = 0; j < 8; j++)
                __stcs((float4*)cout + j*32 + lane, one4);
        }
    }
}

// ---------------- launch (k_main is 4th launch -> gets the ncu slot) ----------------
extern "C" void kernel_launch(void* const* d_in, const int* in_sizes, int n_in,
                              void* d_out, int out_size) {
    const float* q  = (const float*)d_in[0];
    const float* k  = (const float*)d_in[1];
    const float* wq = (const float*)d_in[2];
    const float* bq = (const float*)d_in[3];
    const float* wk = (const float*)d_in[4];
    const float* bk = (const float*)d_in[5];
    const float* pn = (const float*)d_in[6];
    const float* pb = (const float*)d_in[7];

    float* out        = (float*)d_out;
    float* out_coef   = out;
    float* out_approx = out + (size_t)ROWS_TOT*RNn;
    float* out_mask   = out_approx + (size_t)ROWS_TOT*Nn;

    k_prep<<<2048, 256>>>(q, k, wq, bq, wk, bk, pb);
    k_kp2_part<<<dim3(BHn, 8, 2), 256>>>(pn);
    k_kp2_red<<<1536, 256>>>();
    k_main<<<ROWS_TOT/8, 128>>>(out_coef, out_approx, out_mask);
}